// round 1
// baseline (speedup 1.0000x reference)
#include <cuda_runtime.h>
#include <math.h>

// Problem dims
#define LQ   4096      // tokens (64x64)
#define DMODEL 576     // 9*64
#define TD   1728      // 3*DMODEL
#define NHEAD 8
#define DHEAD 72
#define OUTC 128

// ---------------- scratch (static device globals; no allocations) ----------------
__device__ float g_x[LQ * DMODEL];     // unfolded input  [L, D]
__device__ float g_qkv[LQ * TD];       // qkv             [L, 3D]
__device__ float g_o[LQ * DMODEL];     // attention out   [L, D]
__device__ float g_y[LQ * DMODEL];     // proj + residual [L, D]

// ---------------- unfold 3x3 stride 2 pad 1 ----------------
__global__ void unfold_kernel(const float* __restrict__ fea) {
    int idx = blockIdx.x * blockDim.x + threadIdx.x;
    if (idx >= LQ * DMODEL) return;
    int l = idx / DMODEL;
    int d = idx - l * DMODEL;
    int c = d / 9;
    int k = d - c * 9;
    int ki = k / 3, kj = k - ki * 3;
    int oh = l >> 6, ow = l & 63;
    int ih = 2 * oh + ki - 1;
    int iw = 2 * ow + kj - 1;
    float v = 0.f;
    if ((unsigned)ih < 128u && (unsigned)iw < 128u)
        v = fea[(c * 128 + ih) * 128 + iw];
    g_x[idx] = v;
}

// ---------------- generic tiled SGEMM ----------------
// C[M,N] = A[M,K] @ B   (B row-major [K,N] if TRANSB==0, else B is [N,K] row-major)
// EPI: 0 = +bias; 1 = +bias + residual R; 2 = silu + transposed store (C[n*M+m]), no bias
// BM=BN=64, BK=16, 256 threads, 4x4 microtile. Requires M%64==0, N%64==0, K%16==0.
template <int TRANSB, int EPI>
__global__ __launch_bounds__(256)
void sgemm_kernel(const float* __restrict__ A, const float* __restrict__ B,
                  const float* __restrict__ bias, const float* __restrict__ R,
                  float* __restrict__ C, int M, int N, int K) {
    __shared__ float As[16 * 68];   // As[k][m], stride 68 (pad vs bank conflicts)
    __shared__ float Bs[16 * 68];   // Bs[k][n], stride 68

    const int tid = threadIdx.x;
    const int tx = tid & 15;
    const int ty = tid >> 4;
    const int m0 = blockIdx.y * 64;
    const int n0 = blockIdx.x * 64;

    float acc[4][4] = {};

    for (int k0 = 0; k0 < K; k0 += 16) {
        // load A tile 64x16 (transposed into smem)
        {
            int row = tid >> 2, ch = tid & 3;
            float4 a = *(const float4*)&A[(size_t)(m0 + row) * K + k0 + ch * 4];
            As[(ch * 4 + 0) * 68 + row] = a.x;
            As[(ch * 4 + 1) * 68 + row] = a.y;
            As[(ch * 4 + 2) * 68 + row] = a.z;
            As[(ch * 4 + 3) * 68 + row] = a.w;
        }
        // load B tile 16x64
        if (TRANSB) {
            int nn = tid >> 2, ch = tid & 3;
            float4 b = *(const float4*)&B[(size_t)(n0 + nn) * K + k0 + ch * 4];
            Bs[(ch * 4 + 0) * 68 + nn] = b.x;
            Bs[(ch * 4 + 1) * 68 + nn] = b.y;
            Bs[(ch * 4 + 2) * 68 + nn] = b.z;
            Bs[(ch * 4 + 3) * 68 + nn] = b.w;
        } else {
            int kk = tid >> 4, ch = tid & 15;
            *(float4*)&Bs[kk * 68 + ch * 4] =
                *(const float4*)&B[(size_t)(k0 + kk) * N + n0 + ch * 4];
        }
        __syncthreads();

        #pragma unroll
        for (int kk = 0; kk < 16; kk++) {
            float4 a4 = *(const float4*)&As[kk * 68 + 4 * ty];
            float4 b4 = *(const float4*)&Bs[kk * 68 + 4 * tx];
            float av[4] = {a4.x, a4.y, a4.z, a4.w};
            float bv[4] = {b4.x, b4.y, b4.z, b4.w};
            #pragma unroll
            for (int r = 0; r < 4; r++)
                #pragma unroll
                for (int c = 0; c < 4; c++)
                    acc[r][c] += av[r] * bv[c];
        }
        __syncthreads();
    }

    #pragma unroll
    for (int r = 0; r < 4; r++) {
        int m = m0 + 4 * ty + r;
        #pragma unroll
        for (int c = 0; c < 4; c++) {
            int n = n0 + 4 * tx + c;
            float v = acc[r][c];
            if (EPI == 0) {
                C[(size_t)m * N + n] = v + bias[n];
            } else if (EPI == 1) {
                C[(size_t)m * N + n] = v + bias[n] + R[(size_t)m * N + n];
            } else {
                // silu + transposed store (output is [N, M] = [OUTC, L])
                float s = v / (1.f + __expf(-v));
                C[(size_t)n * M + m] = s;
            }
        }
    }
}

// ---------------- flash attention, fp32 ----------------
// grid: (L/64, NHEAD), 256 threads. QB=KB=64, dh=72.
// smem: Qt[72][*68] | KP (Kt[72][*68] aliased with Ps[64][*68]) | Vs[64][72]
#define ATTN_SMEM_FLOATS (72 * 68 + 72 * 68 + 64 * 72)

__global__ __launch_bounds__(256)
void attn_kernel(const float* __restrict__ qkv, float* __restrict__ o_out) {
    extern __shared__ float sm[];
    float* Qt = sm;                   // [d][i], stride 68
    float* KP = sm + 72 * 68;         // Kt [d][j] stride 68 / Ps [i][j] stride 68
    float* Vs = sm + 2 * 72 * 68;     // [j][e], stride 72

    const int tid = threadIdx.x;
    const int tx = tid & 15;
    const int ty = tid >> 4;
    const int h = blockIdx.y;
    const int q0 = blockIdx.x * 64;
    const float scale = rsqrtf((float)DHEAD);

    // load Q block (pre-scaled), transposed
    for (int idx = tid; idx < 64 * DHEAD; idx += 256) {
        int i = idx / DHEAD;
        int d = idx - i * DHEAD;
        Qt[d * 68 + i] = qkv[(size_t)(q0 + i) * TD + h * DHEAD + d] * scale;
    }

    float m_r[4], l_r[4], o_acc[4][5];
    #pragma unroll
    for (int r = 0; r < 4; r++) {
        m_r[r] = -INFINITY;
        l_r[r] = 0.f;
        #pragma unroll
        for (int g = 0; g < 5; g++) o_acc[r][g] = 0.f;
    }

    for (int kb = 0; kb < 64; kb++) {
        const int k0 = kb * 64;
        __syncthreads();   // previous iter's PV reads of KP/Vs done; Q load done (iter 0)

        // load K (transposed) and V
        for (int idx = tid; idx < 64 * DHEAD; idx += 256) {
            int j = idx / DHEAD;
            int d = idx - j * DHEAD;
            const float* row = &qkv[(size_t)(k0 + j) * TD + h * DHEAD + d];
            KP[d * 68 + j] = row[DMODEL];        // K
            Vs[j * 72 + d] = row[2 * DMODEL];    // V
        }
        __syncthreads();

        // S = Q K^T  (4x4 per thread)
        float s[4][4] = {};
        #pragma unroll 8
        for (int d = 0; d < DHEAD; d++) {
            float4 a4 = *(const float4*)&Qt[d * 68 + 4 * ty];
            float4 b4 = *(const float4*)&KP[d * 68 + 4 * tx];
            float av[4] = {a4.x, a4.y, a4.z, a4.w};
            float bv[4] = {b4.x, b4.y, b4.z, b4.w};
            #pragma unroll
            for (int r = 0; r < 4; r++)
                #pragma unroll
                for (int c = 0; c < 4; c++)
                    s[r][c] += av[r] * bv[c];
        }

        // online softmax (row stats across the 16 tx lanes, width-16 shuffles)
        #pragma unroll
        for (int r = 0; r < 4; r++) {
            float mx = fmaxf(fmaxf(s[r][0], s[r][1]), fmaxf(s[r][2], s[r][3]));
            #pragma unroll
            for (int off = 8; off; off >>= 1)
                mx = fmaxf(mx, __shfl_xor_sync(0xffffffffu, mx, off, 16));
            float mnew = fmaxf(m_r[r], mx);
            float alpha = __expf(m_r[r] - mnew);
            m_r[r] = mnew;
            float rs = 0.f;
            #pragma unroll
            for (int c = 0; c < 4; c++) {
                s[r][c] = __expf(s[r][c] - mnew);
                rs += s[r][c];
            }
            #pragma unroll
            for (int off = 8; off; off >>= 1)
                rs += __shfl_xor_sync(0xffffffffu, rs, off, 16);
            l_r[r] = l_r[r] * alpha + rs;
            #pragma unroll
            for (int g = 0; g < 5; g++) o_acc[r][g] *= alpha;
        }

        __syncthreads();   // all S reads of Kt complete before overwriting with P
        #pragma unroll
        for (int r = 0; r < 4; r++)
            *(float4*)&KP[(4 * ty + r) * 68 + 4 * tx] =
                make_float4(s[r][0], s[r][1], s[r][2], s[r][3]);
        __syncthreads();

        // O += P V   (rows 4*ty.., cols tx+16g)
        const bool g4 = (tx < 8);
        #pragma unroll 4
        for (int j = 0; j < 64; j += 4) {
            float P[4][4];
            #pragma unroll
            for (int r = 0; r < 4; r++) {
                float4 p4 = *(const float4*)&KP[(4 * ty + r) * 68 + j];
                P[r][0] = p4.x; P[r][1] = p4.y; P[r][2] = p4.z; P[r][3] = p4.w;
            }
            #pragma unroll
            for (int jj = 0; jj < 4; jj++) {
                const float* vrow = &Vs[(j + jj) * 72];
                float v0 = vrow[tx];
                float v1 = vrow[tx + 16];
                float v2 = vrow[tx + 32];
                float v3 = vrow[tx + 48];
                float v4 = g4 ? vrow[tx + 64] : 0.f;
                #pragma unroll
                for (int r = 0; r < 4; r++) {
                    float p = P[r][jj];
                    o_acc[r][0] += p * v0;
                    o_acc[r][1] += p * v1;
                    o_acc[r][2] += p * v2;
                    o_acc[r][3] += p * v3;
                    o_acc[r][4] += p * v4;
                }
            }
        }
    }

    // write O / l
    #pragma unroll
    for (int r = 0; r < 4; r++) {
        float inv = 1.f / l_r[r];
        int row = q0 + 4 * ty + r;
        float* dst = &o_out[(size_t)row * DMODEL + h * DHEAD];
        dst[tx]      = o_acc[r][0] * inv;
        dst[tx + 16] = o_acc[r][1] * inv;
        dst[tx + 32] = o_acc[r][2] * inv;
        dst[tx + 48] = o_acc[r][3] * inv;
        if (tx < 8) dst[tx + 64] = o_acc[r][4] * inv;
    }
}

// ---------------- launch ----------------
extern "C" void kernel_launch(void* const* d_in, const int* in_sizes, int n_in,
                              void* d_out, int out_size) {
    const float* fea    = (const float*)d_in[0];
    const float* w_qkv  = (const float*)d_in[1];
    const float* b_qkv  = (const float*)d_in[2];
    const float* w_out  = (const float*)d_in[3];
    const float* b_out  = (const float*)d_in[4];
    const float* conv_w = (const float*)d_in[5];
    float* out = (float*)d_out;

    float *px, *pqkv, *po, *py;
    cudaGetSymbolAddress((void**)&px,   g_x);
    cudaGetSymbolAddress((void**)&pqkv, g_qkv);
    cudaGetSymbolAddress((void**)&po,   g_o);
    cudaGetSymbolAddress((void**)&py,   g_y);

    // 1) unfold
    unfold_kernel<<<(LQ * DMODEL + 255) / 256, 256>>>(fea);

    // 2) qkv = x @ w_qkv + b_qkv      [4096,576]x[576,1728]
    sgemm_kernel<0, 0><<<dim3(TD / 64, LQ / 64), 256>>>(
        px, w_qkv, b_qkv, nullptr, pqkv, LQ, TD, DMODEL);

    // 3) flash attention
    cudaFuncSetAttribute(attn_kernel, cudaFuncAttributeMaxDynamicSharedMemorySize,
                         ATTN_SMEM_FLOATS * (int)sizeof(float));
    attn_kernel<<<dim3(LQ / 64, NHEAD), 256, ATTN_SMEM_FLOATS * sizeof(float)>>>(pqkv, po);

    // 4) y = o @ w_out + b_out + x    [4096,576]x[576,576]
    sgemm_kernel<0, 1><<<dim3(DMODEL / 64, LQ / 64), 256>>>(
        po, w_out, b_out, px, py, LQ, DMODEL, DMODEL);

    // 5) out = silu(y @ conv_w^T), stored as [128, 4096]
    sgemm_kernel<1, 2><<<dim3(OUTC / 64, LQ / 64), 256>>>(
        py, conv_w, nullptr, nullptr, out, LQ, OUTC, DMODEL);
}

// round 2
// speedup vs baseline: 3.5474x; 3.5474x over previous
#include <cuda_runtime.h>
#include <math.h>
#include <stdint.h>

#define LQ     4096
#define DMODEL 576
#define TD     1728
#define NHEAD  8
#define DHEAD  72
#define OUTC   128

// ---------------- scratch ----------------
__device__ float g_x[LQ * DMODEL];
__device__ float g_qkv[LQ * TD];
__device__ float g_o[LQ * DMODEL];
__device__ float g_y[LQ * DMODEL];

// ---------------- helpers ----------------
__device__ __forceinline__ float tf32r(float x) {
    uint32_t u;
    asm("cvt.rna.tf32.f32 %0, %1;" : "=r"(u) : "f"(x));
    return __uint_as_float(u);
}

__device__ __forceinline__ void mma8(float* c, float a0, float a1, float a2, float a3,
                                     float b0, float b1) {
    asm volatile(
        "mma.sync.aligned.m16n8k8.row.col.f32.tf32.tf32.f32 "
        "{%0,%1,%2,%3}, {%4,%5,%6,%7}, {%8,%9}, {%0,%1,%2,%3};\n"
        : "+f"(c[0]), "+f"(c[1]), "+f"(c[2]), "+f"(c[3])
        : "r"(__float_as_uint(a0)), "r"(__float_as_uint(a1)),
          "r"(__float_as_uint(a2)), "r"(__float_as_uint(a3)),
          "r"(__float_as_uint(b0)), "r"(__float_as_uint(b1)));
}

// ---------------- unfold 3x3 stride 2 pad 1 ----------------
__global__ void unfold_kernel(const float* __restrict__ fea) {
    int idx = blockIdx.x * blockDim.x + threadIdx.x;
    if (idx >= LQ * DMODEL) return;
    int l = idx / DMODEL;
    int d = idx - l * DMODEL;
    int c = d / 9;
    int k = d - c * 9;
    int ki = k / 3, kj = k - ki * 3;
    int oh = l >> 6, ow = l & 63;
    int ih = 2 * oh + ki - 1;
    int iw = 2 * ow + kj - 1;
    float v = 0.f;
    if ((unsigned)ih < 128u && (unsigned)iw < 128u)
        v = fea[(c * 128 + ih) * 128 + iw];
    g_x[idx] = v;
}

// ---------------- TF32 tensor-core GEMM ----------------
// C[M,N] = A[M,K] @ B  (B row-major [K,N] if TRANSB==0, else [N,K])
// EPI: 0 = +bias; 1 = +bias+residual; 2 = silu + transposed store C[n*M+m]
// Block tile 128x64, BK=32, 256 threads (8 warps as 4m x 2n, warp tile 32x32).
template <int TRANSB, int EPI>
__global__ __launch_bounds__(256)
void gemm_tf32(const float* __restrict__ A, const float* __restrict__ B,
               const float* __restrict__ bias, const float* __restrict__ R,
               float* __restrict__ C, int M, int N, int K) {
    __shared__ float As[128 * 36];  // [m][k] stride 36
    __shared__ float Bs[32 * 72];   // [k][n] stride 72

    const int tid = threadIdx.x;
    const int lane = tid & 31;
    const int wid = tid >> 5;
    const int g = lane >> 2, t = lane & 3;
    const int wm = wid >> 1, wn = wid & 1;
    const int m0 = blockIdx.y * 128, n0 = blockIdx.x * 64;

    float acc[2][4][4] = {};

    for (int k0 = 0; k0 < K; k0 += 32) {
        // A tile 128x32
        #pragma unroll
        for (int i = 0; i < 4; i++) {
            int idx = tid + i * 256;
            int r = idx >> 3, c = (idx & 7) * 4;
            float4 v = *(const float4*)&A[(size_t)(m0 + r) * K + k0 + c];
            As[r * 36 + c + 0] = tf32r(v.x);
            As[r * 36 + c + 1] = tf32r(v.y);
            As[r * 36 + c + 2] = tf32r(v.z);
            As[r * 36 + c + 3] = tf32r(v.w);
        }
        // B tile 32x64
        if (!TRANSB) {
            #pragma unroll
            for (int i = 0; i < 2; i++) {
                int idx = tid + i * 256;
                int r = idx >> 4, c = (idx & 15) * 4;
                float4 v = *(const float4*)&B[(size_t)(k0 + r) * N + n0 + c];
                *(float4*)&Bs[r * 72 + c] =
                    make_float4(tf32r(v.x), tf32r(v.y), tf32r(v.z), tf32r(v.w));
            }
        } else {
            #pragma unroll
            for (int i = 0; i < 2; i++) {
                int idx = tid + i * 256;
                int n = idx >> 3, c = (idx & 7) * 4;
                float4 v = *(const float4*)&B[(size_t)(n0 + n) * K + k0 + c];
                Bs[(c + 0) * 72 + n] = tf32r(v.x);
                Bs[(c + 1) * 72 + n] = tf32r(v.y);
                Bs[(c + 2) * 72 + n] = tf32r(v.z);
                Bs[(c + 3) * 72 + n] = tf32r(v.w);
            }
        }
        __syncthreads();

        #pragma unroll
        for (int kk = 0; kk < 4; kk++) {
            const int kc = kk * 8;
            float a[2][4], b[4][2];
            #pragma unroll
            for (int am = 0; am < 2; am++) {
                int r = wm * 32 + am * 16;
                a[am][0] = As[(r + g) * 36 + kc + t];
                a[am][1] = As[(r + g + 8) * 36 + kc + t];
                a[am][2] = As[(r + g) * 36 + kc + t + 4];
                a[am][3] = As[(r + g + 8) * 36 + kc + t + 4];
            }
            #pragma unroll
            for (int j = 0; j < 4; j++) {
                int cb = wn * 32 + 8 * j + g;
                b[j][0] = Bs[(kc + t) * 72 + cb];
                b[j][1] = Bs[(kc + t + 4) * 72 + cb];
            }
            #pragma unroll
            for (int am = 0; am < 2; am++)
                #pragma unroll
                for (int j = 0; j < 4; j++)
                    mma8(acc[am][j], a[am][0], a[am][1], a[am][2], a[am][3],
                         b[j][0], b[j][1]);
        }
        __syncthreads();
    }

    // epilogue
    #pragma unroll
    for (int am = 0; am < 2; am++) {
        int r0 = m0 + wm * 32 + am * 16 + g;
        int r1 = r0 + 8;
        #pragma unroll
        for (int j = 0; j < 4; j++) {
            int c0 = n0 + wn * 32 + 8 * j + 2 * t;
            float v00 = acc[am][j][0], v01 = acc[am][j][1];
            float v10 = acc[am][j][2], v11 = acc[am][j][3];
            if (EPI == 0) {
                C[(size_t)r0 * N + c0]     = v00 + bias[c0];
                C[(size_t)r0 * N + c0 + 1] = v01 + bias[c0 + 1];
                C[(size_t)r1 * N + c0]     = v10 + bias[c0];
                C[(size_t)r1 * N + c0 + 1] = v11 + bias[c0 + 1];
            } else if (EPI == 1) {
                C[(size_t)r0 * N + c0]     = v00 + bias[c0]     + R[(size_t)r0 * N + c0];
                C[(size_t)r0 * N + c0 + 1] = v01 + bias[c0 + 1] + R[(size_t)r0 * N + c0 + 1];
                C[(size_t)r1 * N + c0]     = v10 + bias[c0]     + R[(size_t)r1 * N + c0];
                C[(size_t)r1 * N + c0 + 1] = v11 + bias[c0 + 1] + R[(size_t)r1 * N + c0 + 1];
            } else {
                float s00 = v00 / (1.f + __expf(-v00));
                float s01 = v01 / (1.f + __expf(-v01));
                float s10 = v10 / (1.f + __expf(-v10));
                float s11 = v11 / (1.f + __expf(-v11));
                C[(size_t)(c0)     * M + r0] = s00;
                C[(size_t)(c0 + 1) * M + r0] = s01;
                C[(size_t)(c0)     * M + r1] = s10;
                C[(size_t)(c0 + 1) * M + r1] = s11;
            }
        }
    }
}

// ---------------- TF32 flash attention ----------------
// grid (LQ/128, NHEAD), 256 threads (8 warps, each owns 16 q-rows).
// smem: Ks[64][*76] | Vs[64][*72] | Ps[128][*76]
#define ATTN_SMEM_FLOATS (64 * 76 + 64 * 72 + 128 * 76)

__global__ __launch_bounds__(256)
void attn_tf32(const float* __restrict__ qkv, float* __restrict__ o_out) {
    extern __shared__ float sm[];
    float* Ks = sm;
    float* Vs = sm + 64 * 76;
    float* Ps = sm + 64 * 76 + 64 * 72;

    const int tid = threadIdx.x;
    const int lane = tid & 31;
    const int wid = tid >> 5;
    const int g = lane >> 2, t = lane & 3;
    const int h = blockIdx.y;
    const int q0 = blockIdx.x * 128;
    const int wr = wid * 16;
    const float scale = rsqrtf((float)DHEAD);

    // Q fragments (row-major A, m16k8 atoms over dh=72 -> 9 atoms), pre-scaled
    float qa[9][4];
    {
        const float* qb  = qkv + (size_t)(q0 + wr + g) * TD + h * DHEAD;
        const float* qb8 = qb + 8 * (size_t)TD;
        #pragma unroll
        for (int ka = 0; ka < 9; ka++) {
            int c = ka * 8 + t;
            qa[ka][0] = tf32r(qb[c] * scale);
            qa[ka][1] = tf32r(qb8[c] * scale);
            qa[ka][2] = tf32r(qb[c + 4] * scale);
            qa[ka][3] = tf32r(qb8[c + 4] * scale);
        }
    }

    float oacc[9][4] = {};
    float m0 = -INFINITY, m1 = -INFINITY, l0 = 0.f, l1 = 0.f;

    for (int kb = 0; kb < 64; kb++) {
        const int k0 = kb * 64;
        __syncthreads();  // protect Ks/Vs from previous iteration's readers

        // load K,V tiles (tf32-rounded)
        for (int idx = tid; idx < 64 * 36; idx += 256) {
            int r = idx / 36;
            int c2 = (idx - r * 36) * 2;
            const float* p = qkv + (size_t)(k0 + r) * TD + h * DHEAD + c2;
            float2 kv = *(const float2*)(p + DMODEL);
            float2 vv = *(const float2*)(p + 2 * DMODEL);
            Ks[r * 76 + c2]     = tf32r(kv.x);
            Ks[r * 76 + c2 + 1] = tf32r(kv.y);
            Vs[r * 72 + c2]     = tf32r(vv.x);
            Vs[r * 72 + c2 + 1] = tf32r(vv.y);
        }
        __syncthreads();

        // S = Q K^T  (8 n-atoms over 64 kcols)
        float sc[8][4] = {};
        #pragma unroll
        for (int ka = 0; ka < 9; ka++) {
            #pragma unroll
            for (int j = 0; j < 8; j++) {
                const float* kr = &Ks[(8 * j + g) * 76 + ka * 8 + t];
                mma8(sc[j], qa[ka][0], qa[ka][1], qa[ka][2], qa[ka][3],
                     kr[0], kr[4]);
            }
        }

        // online softmax: thread owns rows (wr+g) via c0/c1 and (wr+g+8) via c2/c3
        float mx0 = -INFINITY, mx1 = -INFINITY;
        #pragma unroll
        for (int j = 0; j < 8; j++) {
            mx0 = fmaxf(mx0, fmaxf(sc[j][0], sc[j][1]));
            mx1 = fmaxf(mx1, fmaxf(sc[j][2], sc[j][3]));
        }
        mx0 = fmaxf(mx0, __shfl_xor_sync(0xffffffffu, mx0, 1));
        mx0 = fmaxf(mx0, __shfl_xor_sync(0xffffffffu, mx0, 2));
        mx1 = fmaxf(mx1, __shfl_xor_sync(0xffffffffu, mx1, 1));
        mx1 = fmaxf(mx1, __shfl_xor_sync(0xffffffffu, mx1, 2));

        float mn0 = fmaxf(m0, mx0), mn1 = fmaxf(m1, mx1);
        float al0 = __expf(m0 - mn0), al1 = __expf(m1 - mn1);
        m0 = mn0; m1 = mn1;

        float s0 = 0.f, s1 = 0.f;
        #pragma unroll
        for (int j = 0; j < 8; j++) {
            sc[j][0] = __expf(sc[j][0] - m0);
            sc[j][1] = __expf(sc[j][1] - m0);
            sc[j][2] = __expf(sc[j][2] - m1);
            sc[j][3] = __expf(sc[j][3] - m1);
            s0 += sc[j][0] + sc[j][1];
            s1 += sc[j][2] + sc[j][3];
        }
        s0 += __shfl_xor_sync(0xffffffffu, s0, 1);
        s0 += __shfl_xor_sync(0xffffffffu, s0, 2);
        s1 += __shfl_xor_sync(0xffffffffu, s1, 1);
        s1 += __shfl_xor_sync(0xffffffffu, s1, 2);
        l0 = l0 * al0 + s0;
        l1 = l1 * al1 + s1;

        #pragma unroll
        for (int j2 = 0; j2 < 9; j2++) {
            oacc[j2][0] *= al0; oacc[j2][1] *= al0;
            oacc[j2][2] *= al1; oacc[j2][3] *= al1;
        }

        // write P fragments (C layout) to smem; warp-private rows
        const int pr0 = (wr + g) * 76, pr1 = (wr + g + 8) * 76;
        #pragma unroll
        for (int j = 0; j < 8; j++) {
            *(float2*)&Ps[pr0 + 8 * j + 2 * t] =
                make_float2(tf32r(sc[j][0]), tf32r(sc[j][1]));
            *(float2*)&Ps[pr1 + 8 * j + 2 * t] =
                make_float2(tf32r(sc[j][2]), tf32r(sc[j][3]));
        }
        __syncwarp();

        // O += P V
        #pragma unroll
        for (int ka = 0; ka < 8; ka++) {
            float p0 = Ps[pr0 + 8 * ka + t];
            float p1 = Ps[pr1 + 8 * ka + t];
            float p2 = Ps[pr0 + 8 * ka + t + 4];
            float p3 = Ps[pr1 + 8 * ka + t + 4];
            #pragma unroll
            for (int j2 = 0; j2 < 9; j2++) {
                const float* vr = &Vs[(8 * ka + t) * 72 + 8 * j2 + g];
                mma8(oacc[j2], p0, p1, p2, p3, vr[0], vr[4 * 72]);
            }
        }
        __syncwarp();
    }

    // finalize
    float i0 = 1.f / l0, i1 = 1.f / l1;
    float* d0 = o_out + (size_t)(q0 + wr + g) * DMODEL + h * DHEAD;
    float* d1 = d0 + 8 * (size_t)DMODEL;
    #pragma unroll
    for (int j2 = 0; j2 < 9; j2++) {
        *(float2*)&d0[8 * j2 + 2 * t] = make_float2(oacc[j2][0] * i0, oacc[j2][1] * i0);
        *(float2*)&d1[8 * j2 + 2 * t] = make_float2(oacc[j2][2] * i1, oacc[j2][3] * i1);
    }
}

// ---------------- launch ----------------
extern "C" void kernel_launch(void* const* d_in, const int* in_sizes, int n_in,
                              void* d_out, int out_size) {
    const float* fea    = (const float*)d_in[0];
    const float* w_qkv  = (const float*)d_in[1];
    const float* b_qkv  = (const float*)d_in[2];
    const float* w_out  = (const float*)d_in[3];
    const float* b_out  = (const float*)d_in[4];
    const float* conv_w = (const float*)d_in[5];
    float* out = (float*)d_out;

    float *px, *pqkv, *po, *py;
    cudaGetSymbolAddress((void**)&px,   g_x);
    cudaGetSymbolAddress((void**)&pqkv, g_qkv);
    cudaGetSymbolAddress((void**)&po,   g_o);
    cudaGetSymbolAddress((void**)&py,   g_y);

    // 1) unfold
    unfold_kernel<<<(LQ * DMODEL + 255) / 256, 256>>>(fea);

    // 2) qkv = x @ w_qkv + b
    gemm_tf32<0, 0><<<dim3(TD / 64, LQ / 128), 256>>>(
        px, w_qkv, b_qkv, nullptr, pqkv, LQ, TD, DMODEL);

    // 3) attention
    cudaFuncSetAttribute(attn_tf32, cudaFuncAttributeMaxDynamicSharedMemorySize,
                         ATTN_SMEM_FLOATS * (int)sizeof(float));
    attn_tf32<<<dim3(LQ / 128, NHEAD), 256, ATTN_SMEM_FLOATS * sizeof(float)>>>(pqkv, po);

    // 4) y = o @ w_out + b + x
    gemm_tf32<0, 1><<<dim3(DMODEL / 64, LQ / 128), 256>>>(
        po, w_out, b_out, px, py, LQ, DMODEL, DMODEL);

    // 5) out = silu(y @ conv_w^T), stored [128, 4096]
    gemm_tf32<1, 2><<<dim3(OUTC / 64, LQ / 128), 256>>>(
        py, conv_w, nullptr, nullptr, out, LQ, OUTC, DMODEL);
}

// round 3
// speedup vs baseline: 3.5768x; 1.0083x over previous
#include <cuda_runtime.h>
#include <math.h>
#include <stdint.h>

#define LQ     4096
#define DMODEL 576
#define TD     1728
#define NHEAD  8
#define DHEAD  72
#define OUTC   128

// ---------------- scratch ----------------
__device__ float g_x[LQ * DMODEL];
__device__ float g_qkv[LQ * TD];
__device__ float g_o[LQ * DMODEL];
__device__ float g_y[LQ * DMODEL];

// ---------------- helpers ----------------
__device__ __forceinline__ float tf32r(float x) {
    uint32_t u;
    asm("cvt.rna.tf32.f32 %0, %1;" : "=r"(u) : "f"(x));
    return __uint_as_float(u);
}

__device__ __forceinline__ void mma8(float* c, float a0, float a1, float a2, float a3,
                                     float b0, float b1) {
    asm volatile(
        "mma.sync.aligned.m16n8k8.row.col.f32.tf32.tf32.f32 "
        "{%0,%1,%2,%3}, {%4,%5,%6,%7}, {%8,%9}, {%0,%1,%2,%3};\n"
        : "+f"(c[0]), "+f"(c[1]), "+f"(c[2]), "+f"(c[3])
        : "r"(__float_as_uint(a0)), "r"(__float_as_uint(a1)),
          "r"(__float_as_uint(a2)), "r"(__float_as_uint(a3)),
          "r"(__float_as_uint(b0)), "r"(__float_as_uint(b1)));
}

__device__ __forceinline__ void cp16(uint32_t dst, const float* src) {
    asm volatile("cp.async.cg.shared.global [%0], [%1], 16;\n" :: "r"(dst), "l"(src));
}
__device__ __forceinline__ void cp_commit() { asm volatile("cp.async.commit_group;\n"); }
__device__ __forceinline__ void cp_wait0()  { asm volatile("cp.async.wait_group 0;\n"); }

// ---------------- unfold 3x3 stride 2 pad 1 ----------------
__global__ void unfold_kernel(const float* __restrict__ fea) {
    int idx = blockIdx.x * blockDim.x + threadIdx.x;
    if (idx >= LQ * DMODEL) return;
    int l = idx / DMODEL;
    int d = idx - l * DMODEL;
    int c = d / 9;
    int k = d - c * 9;
    int ki = k / 3, kj = k - ki * 3;
    int oh = l >> 6, ow = l & 63;
    int ih = 2 * oh + ki - 1;
    int iw = 2 * ow + kj - 1;
    float v = 0.f;
    if ((unsigned)ih < 128u && (unsigned)iw < 128u)
        v = fea[(c * 128 + ih) * 128 + iw];
    g_x[idx] = v;
}

// ---------------- TF32 GEMM, cp.async double-buffered ----------------
// C[M,N] = A[M,K] @ B  (TRANSB: B is [N,K]); block 128x64, BK=32, 256 thr,
// 8 warps (4m x 2n), warp tile 32x32. smem dynamic: As[2][128*36] Bs[2][2304]
#define GEMM_SMEM_BYTES ((2 * 128 * 36 + 2 * 2304) * 4)

template <int TRANSB, int EPI>
__global__ __launch_bounds__(256)
void gemm_tf32(const float* __restrict__ A, const float* __restrict__ B,
               const float* __restrict__ bias, const float* __restrict__ R,
               float* __restrict__ C, int M, int N, int K) {
    extern __shared__ float sm[];
    float* As = sm;                  // [2][128*36]
    float* Bs = sm + 2 * 128 * 36;   // [2][2304]
    const uint32_t as_b = (uint32_t)__cvta_generic_to_shared(As);
    const uint32_t bs_b = (uint32_t)__cvta_generic_to_shared(Bs);

    const int tid = threadIdx.x;
    const int lane = tid & 31;
    const int wid = tid >> 5;
    const int g = lane >> 2, t = lane & 3;
    const int wm = wid >> 1, wn = wid & 1;
    const int m0 = blockIdx.y * 128, n0 = blockIdx.x * 64;

    float acc[2][4][4] = {};

    auto loadTiles = [&](int k0, int buf) {
        #pragma unroll
        for (int i = 0; i < 4; i++) {
            int idx = tid + i * 256;
            int r = idx >> 3, c = (idx & 7) * 4;
            cp16(as_b + (uint32_t)(buf * 128 * 36 + r * 36 + c) * 4,
                 &A[(size_t)(m0 + r) * K + k0 + c]);
        }
        if (!TRANSB) {
            #pragma unroll
            for (int i = 0; i < 2; i++) {
                int idx = tid + i * 256;
                int r = idx >> 4, c = (idx & 15) * 4;
                cp16(bs_b + (uint32_t)(buf * 2304 + r * 72 + c) * 4,
                     &B[(size_t)(k0 + r) * N + n0 + c]);
            }
        } else {
            #pragma unroll
            for (int i = 0; i < 2; i++) {
                int idx = tid + i * 256;
                int r = idx >> 3, c = (idx & 7) * 4;
                cp16(bs_b + (uint32_t)(buf * 2304 + r * 36 + c) * 4,
                     &B[(size_t)(n0 + r) * K + k0 + c]);
            }
        }
        cp_commit();
    };

    const int nk = K / 32;
    loadTiles(0, 0);

    for (int ik = 0; ik < nk; ik++) {
        cp_wait0();
        __syncthreads();
        if (ik + 1 < nk) loadTiles((ik + 1) * 32, (ik + 1) & 1);

        const float* as = As + (ik & 1) * 128 * 36;
        const float* bs = Bs + (ik & 1) * 2304;

        #pragma unroll
        for (int kk = 0; kk < 4; kk++) {
            const int kc = kk * 8;
            float a[2][4], b[4][2];
            #pragma unroll
            for (int am = 0; am < 2; am++) {
                int r = wm * 32 + am * 16;
                a[am][0] = tf32r(as[(r + g) * 36 + kc + t]);
                a[am][1] = tf32r(as[(r + g + 8) * 36 + kc + t]);
                a[am][2] = tf32r(as[(r + g) * 36 + kc + t + 4]);
                a[am][3] = tf32r(as[(r + g + 8) * 36 + kc + t + 4]);
            }
            #pragma unroll
            for (int j = 0; j < 4; j++) {
                int cb = wn * 32 + 8 * j + g;
                if (!TRANSB) {
                    b[j][0] = tf32r(bs[(kc + t) * 72 + cb]);
                    b[j][1] = tf32r(bs[(kc + t + 4) * 72 + cb]);
                } else {
                    b[j][0] = tf32r(bs[cb * 36 + kc + t]);
                    b[j][1] = tf32r(bs[cb * 36 + kc + t + 4]);
                }
            }
            #pragma unroll
            for (int am = 0; am < 2; am++)
                #pragma unroll
                for (int j = 0; j < 4; j++)
                    mma8(acc[am][j], a[am][0], a[am][1], a[am][2], a[am][3],
                         b[j][0], b[j][1]);
        }
        __syncthreads();
    }

    #pragma unroll
    for (int am = 0; am < 2; am++) {
        int r0 = m0 + wm * 32 + am * 16 + g;
        int r1 = r0 + 8;
        #pragma unroll
        for (int j = 0; j < 4; j++) {
            int c0 = n0 + wn * 32 + 8 * j + 2 * t;
            float v00 = acc[am][j][0], v01 = acc[am][j][1];
            float v10 = acc[am][j][2], v11 = acc[am][j][3];
            if (EPI == 0) {
                C[(size_t)r0 * N + c0]     = v00 + bias[c0];
                C[(size_t)r0 * N + c0 + 1] = v01 + bias[c0 + 1];
                C[(size_t)r1 * N + c0]     = v10 + bias[c0];
                C[(size_t)r1 * N + c0 + 1] = v11 + bias[c0 + 1];
            } else if (EPI == 1) {
                C[(size_t)r0 * N + c0]     = v00 + bias[c0]     + R[(size_t)r0 * N + c0];
                C[(size_t)r0 * N + c0 + 1] = v01 + bias[c0 + 1] + R[(size_t)r0 * N + c0 + 1];
                C[(size_t)r1 * N + c0]     = v10 + bias[c0]     + R[(size_t)r1 * N + c0];
                C[(size_t)r1 * N + c0 + 1] = v11 + bias[c0 + 1] + R[(size_t)r1 * N + c0 + 1];
            } else {
                float s00 = v00 / (1.f + __expf(-v00));
                float s01 = v01 / (1.f + __expf(-v01));
                float s10 = v10 / (1.f + __expf(-v10));
                float s11 = v11 / (1.f + __expf(-v11));
                C[(size_t)(c0)     * M + r0] = s00;
                C[(size_t)(c0 + 1) * M + r0] = s01;
                C[(size_t)(c0)     * M + r1] = s10;
                C[(size_t)(c0 + 1) * M + r1] = s11;
            }
        }
    }
}

// ---------------- TF32 flash attention, cp.async double-buffered K/V ----------------
// grid (LQ/64, NHEAD), 128 threads (4 warps x 16 q-rows).
// smem: Ks[2][64*76] | Vs[2][64*72] | Ps[64*76]
#define KS_STRIDE 76
#define VS_STRIDE 72
#define KS_TILE (64 * KS_STRIDE)
#define VS_TILE (64 * VS_STRIDE)
#define ATTN_SMEM_BYTES ((2 * KS_TILE + 2 * VS_TILE + 64 * KS_STRIDE) * 4)

__global__ __launch_bounds__(128)
void attn_tf32(const float* __restrict__ qkv, float* __restrict__ o_out) {
    extern __shared__ float sm[];
    float* Ks = sm;                            // [2][64*76]
    float* Vs = sm + 2 * KS_TILE;              // [2][64*72]
    float* Ps = sm + 2 * KS_TILE + 2 * VS_TILE;// [64*76]
    const uint32_t ks_b = (uint32_t)__cvta_generic_to_shared(Ks);
    const uint32_t vs_b = (uint32_t)__cvta_generic_to_shared(Vs);

    const int tid = threadIdx.x;
    const int lane = tid & 31;
    const int wid = tid >> 5;
    const int g = lane >> 2, t = lane & 3;
    const int h = blockIdx.y;
    const int q0 = blockIdx.x * 64;
    const int wr = wid * 16;
    const float scale = rsqrtf((float)DHEAD);

    auto loadKV = [&](int kb, int buf) {
        const float* base = qkv + (size_t)(kb * 64) * TD + h * DHEAD;
        #pragma unroll
        for (int i = 0; i < 9; i++) {
            int idx = tid + i * 128;
            int r = idx / 18, c = (idx - r * 18) * 4;
            const float* rp = base + (size_t)r * TD + c;
            cp16(ks_b + (uint32_t)(buf * KS_TILE + r * KS_STRIDE + c) * 4, rp + DMODEL);
            cp16(vs_b + (uint32_t)(buf * VS_TILE + r * VS_STRIDE + c) * 4, rp + 2 * DMODEL);
        }
        cp_commit();
    };

    loadKV(0, 0);

    // Q fragments (pre-scaled, rna-rounded)
    float qa[9][4];
    {
        const float* qb  = qkv + (size_t)(q0 + wr + g) * TD + h * DHEAD;
        const float* qb8 = qb + 8 * (size_t)TD;
        #pragma unroll
        for (int ka = 0; ka < 9; ka++) {
            int c = ka * 8 + t;
            qa[ka][0] = tf32r(qb[c] * scale);
            qa[ka][1] = tf32r(qb8[c] * scale);
            qa[ka][2] = tf32r(qb[c + 4] * scale);
            qa[ka][3] = tf32r(qb8[c + 4] * scale);
        }
    }

    float oacc[9][4] = {};
    float m0 = -INFINITY, m1 = -INFINITY, l0 = 0.f, l1 = 0.f;

    for (int kb = 0; kb < 64; kb++) {
        cp_wait0();
        __syncthreads();
        if (kb + 1 < 64) loadKV(kb + 1, (kb + 1) & 1);

        const float* ks = Ks + (kb & 1) * KS_TILE;
        const float* vs = Vs + (kb & 1) * VS_TILE;

        // S = Q K^T
        float sc[8][4] = {};
        #pragma unroll
        for (int ka = 0; ka < 9; ka++) {
            #pragma unroll
            for (int j = 0; j < 8; j++) {
                const float* kr = &ks[(8 * j + g) * KS_STRIDE + ka * 8 + t];
                mma8(sc[j], qa[ka][0], qa[ka][1], qa[ka][2], qa[ka][3],
                     kr[0], kr[4]);
            }
        }

        // online softmax
        float mx0 = -INFINITY, mx1 = -INFINITY;
        #pragma unroll
        for (int j = 0; j < 8; j++) {
            mx0 = fmaxf(mx0, fmaxf(sc[j][0], sc[j][1]));
            mx1 = fmaxf(mx1, fmaxf(sc[j][2], sc[j][3]));
        }
        mx0 = fmaxf(mx0, __shfl_xor_sync(0xffffffffu, mx0, 1));
        mx0 = fmaxf(mx0, __shfl_xor_sync(0xffffffffu, mx0, 2));
        mx1 = fmaxf(mx1, __shfl_xor_sync(0xffffffffu, mx1, 1));
        mx1 = fmaxf(mx1, __shfl_xor_sync(0xffffffffu, mx1, 2));

        float mn0 = fmaxf(m0, mx0), mn1 = fmaxf(m1, mx1);
        float al0 = __expf(m0 - mn0), al1 = __expf(m1 - mn1);
        m0 = mn0; m1 = mn1;

        float s0 = 0.f, s1 = 0.f;
        #pragma unroll
        for (int j = 0; j < 8; j++) {
            sc[j][0] = __expf(sc[j][0] - m0);
            sc[j][1] = __expf(sc[j][1] - m0);
            sc[j][2] = __expf(sc[j][2] - m1);
            sc[j][3] = __expf(sc[j][3] - m1);
            s0 += sc[j][0] + sc[j][1];
            s1 += sc[j][2] + sc[j][3];
        }
        s0 += __shfl_xor_sync(0xffffffffu, s0, 1);
        s0 += __shfl_xor_sync(0xffffffffu, s0, 2);
        s1 += __shfl_xor_sync(0xffffffffu, s1, 1);
        s1 += __shfl_xor_sync(0xffffffffu, s1, 2);
        l0 = l0 * al0 + s0;
        l1 = l1 * al1 + s1;

        #pragma unroll
        for (int j2 = 0; j2 < 9; j2++) {
            oacc[j2][0] *= al0; oacc[j2][1] *= al0;
            oacc[j2][2] *= al1; oacc[j2][3] *= al1;
        }

        // P fragments via smem (warp-private rows)
        const int pr0 = (wr + g) * KS_STRIDE, pr1 = (wr + g + 8) * KS_STRIDE;
        #pragma unroll
        for (int j = 0; j < 8; j++) {
            *(float2*)&Ps[pr0 + 8 * j + 2 * t] =
                make_float2(tf32r(sc[j][0]), tf32r(sc[j][1]));
            *(float2*)&Ps[pr1 + 8 * j + 2 * t] =
                make_float2(tf32r(sc[j][2]), tf32r(sc[j][3]));
        }
        __syncwarp();

        // O += P V
        #pragma unroll
        for (int ka = 0; ka < 8; ka++) {
            float p0 = Ps[pr0 + 8 * ka + t];
            float p1 = Ps[pr1 + 8 * ka + t];
            float p2 = Ps[pr0 + 8 * ka + t + 4];
            float p3 = Ps[pr1 + 8 * ka + t + 4];
            #pragma unroll
            for (int j2 = 0; j2 < 9; j2++) {
                const float* vr = &vs[(8 * ka + t) * VS_STRIDE + 8 * j2 + g];
                mma8(oacc[j2], p0, p1, p2, p3, vr[0], vr[4 * VS_STRIDE]);
            }
        }
        __syncwarp();
    }

    // finalize
    float i0 = 1.f / l0, i1 = 1.f / l1;
    float* d0 = o_out + (size_t)(q0 + wr + g) * DMODEL + h * DHEAD;
    float* d1 = d0 + 8 * (size_t)DMODEL;
    #pragma unroll
    for (int j2 = 0; j2 < 9; j2++) {
        *(float2*)&d0[8 * j2 + 2 * t] = make_float2(oacc[j2][0] * i0, oacc[j2][1] * i0);
        *(float2*)&d1[8 * j2 + 2 * t] = make_float2(oacc[j2][2] * i1, oacc[j2][3] * i1);
    }
}

// ---------------- launch ----------------
extern "C" void kernel_launch(void* const* d_in, const int* in_sizes, int n_in,
                              void* d_out, int out_size) {
    const float* fea    = (const float*)d_in[0];
    const float* w_qkv  = (const float*)d_in[1];
    const float* b_qkv  = (const float*)d_in[2];
    const float* w_out  = (const float*)d_in[3];
    const float* b_out  = (const float*)d_in[4];
    const float* conv_w = (const float*)d_in[5];
    float* out = (float*)d_out;

    float *px, *pqkv, *po, *py;
    cudaGetSymbolAddress((void**)&px,   g_x);
    cudaGetSymbolAddress((void**)&pqkv, g_qkv);
    cudaGetSymbolAddress((void**)&po,   g_o);
    cudaGetSymbolAddress((void**)&py,   g_y);

    cudaFuncSetAttribute(gemm_tf32<0, 0>, cudaFuncAttributeMaxDynamicSharedMemorySize, GEMM_SMEM_BYTES);
    cudaFuncSetAttribute(gemm_tf32<0, 1>, cudaFuncAttributeMaxDynamicSharedMemorySize, GEMM_SMEM_BYTES);
    cudaFuncSetAttribute(gemm_tf32<1, 2>, cudaFuncAttributeMaxDynamicSharedMemorySize, GEMM_SMEM_BYTES);
    cudaFuncSetAttribute(attn_tf32, cudaFuncAttributeMaxDynamicSharedMemorySize, ATTN_SMEM_BYTES);

    // 1) unfold
    unfold_kernel<<<(LQ * DMODEL + 255) / 256, 256>>>(fea);

    // 2) qkv = x @ w_qkv + b
    gemm_tf32<0, 0><<<dim3(TD / 64, LQ / 128), 256, GEMM_SMEM_BYTES>>>(
        px, w_qkv, b_qkv, nullptr, pqkv, LQ, TD, DMODEL);

    // 3) attention
    attn_tf32<<<dim3(LQ / 64, NHEAD), 128, ATTN_SMEM_BYTES>>>(pqkv, po);

    // 4) y = o @ w_out + b + x
    gemm_tf32<0, 1><<<dim3(DMODEL / 64, LQ / 128), 256, GEMM_SMEM_BYTES>>>(
        po, w_out, b_out, px, py, LQ, DMODEL, DMODEL);

    // 5) out = silu(y @ conv_w^T), stored [128, 4096]
    gemm_tf32<1, 2><<<dim3(OUTC / 64, LQ / 128), 256, GEMM_SMEM_BYTES>>>(
        py, conv_w, nullptr, nullptr, out, LQ, OUTC, DMODEL);
}

// round 5
// speedup vs baseline: 4.0142x; 1.1223x over previous
#include <cuda_runtime.h>
#include <math.h>
#include <stdint.h>

#define LQ     4096
#define DMODEL 576
#define TD     1728
#define NHEAD  8
#define DHEAD  72
#define OUTC   128

// ---------------- scratch ----------------
__device__ float g_x[LQ * DMODEL];
__device__ float g_qkv[LQ * TD];
__device__ float g_o[LQ * DMODEL];
__device__ float g_y[LQ * DMODEL];

// ---------------- helpers ----------------
__device__ __forceinline__ float tf32r(float x) {
    uint32_t u;
    asm("cvt.rna.tf32.f32 %0, %1;" : "=r"(u) : "f"(x));
    return __uint_as_float(u);
}

__device__ __forceinline__ void mma8(float* c, float a0, float a1, float a2, float a3,
                                     float b0, float b1) {
    asm volatile(
        "mma.sync.aligned.m16n8k8.row.col.f32.tf32.tf32.f32 "
        "{%0,%1,%2,%3}, {%4,%5,%6,%7}, {%8,%9}, {%0,%1,%2,%3};\n"
        : "+f"(c[0]), "+f"(c[1]), "+f"(c[2]), "+f"(c[3])
        : "r"(__float_as_uint(a0)), "r"(__float_as_uint(a1)),
          "r"(__float_as_uint(a2)), "r"(__float_as_uint(a3)),
          "r"(__float_as_uint(b0)), "r"(__float_as_uint(b1)));
}

__device__ __forceinline__ void cp16(uint32_t dst, const float* src) {
    asm volatile("cp.async.cg.shared.global [%0], [%1], 16;\n" :: "r"(dst), "l"(src));
}
__device__ __forceinline__ void cp_commit() { asm volatile("cp.async.commit_group;\n"); }
__device__ __forceinline__ void cp_wait0()  { asm volatile("cp.async.wait_group 0;\n"); }
__device__ __forceinline__ void cp_wait1()  { asm volatile("cp.async.wait_group 1;\n"); }

// ---------------- unfold 3x3 stride 2 pad 1 ----------------
__global__ void unfold_kernel(const float* __restrict__ fea) {
    int idx = blockIdx.x * blockDim.x + threadIdx.x;
    if (idx >= LQ * DMODEL) return;
    int l = idx / DMODEL;
    int d = idx - l * DMODEL;
    int c = d / 9;
    int k = d - c * 9;
    int ki = k / 3, kj = k - ki * 3;
    int oh = l >> 6, ow = l & 63;
    int ih = 2 * oh + ki - 1;
    int iw = 2 * ow + kj - 1;
    float v = 0.f;
    if ((unsigned)ih < 128u && (unsigned)iw < 128u)
        v = fea[(c * 128 + ih) * 128 + iw];
    g_x[idx] = v;
}

// ---------------- TF32 GEMM, 3-stage cp.async pipeline ----------------
// C[M,N] = A[M,K] @ B  (TRANSB: B is [N,K]); block 128x64, BK=32, 256 thr.
#define GEMM_SMEM_BYTES ((3 * 128 * 36 + 3 * 2304) * 4)

template <int TRANSB, int EPI>
__global__ __launch_bounds__(256)
void gemm_tf32(const float* __restrict__ A, const float* __restrict__ B,
               const float* __restrict__ bias, const float* __restrict__ R,
               float* __restrict__ C, int M, int N, int K) {
    extern __shared__ float sm[];
    float* As = sm;                  // [3][128*36]
    float* Bs = sm + 3 * 128 * 36;   // [3][2304]
    const uint32_t as_b = (uint32_t)__cvta_generic_to_shared(As);
    const uint32_t bs_b = (uint32_t)__cvta_generic_to_shared(Bs);

    const int tid = threadIdx.x;
    const int lane = tid & 31;
    const int wid = tid >> 5;
    const int g = lane >> 2, t = lane & 3;
    const int wm = wid >> 1, wn = wid & 1;
    const int m0 = blockIdx.y * 128, n0 = blockIdx.x * 64;

    float acc[2][4][4] = {};

    auto loadTiles = [&](int k0, int buf) {
        #pragma unroll
        for (int i = 0; i < 4; i++) {
            int idx = tid + i * 256;
            int r = idx >> 3, c = (idx & 7) * 4;
            cp16(as_b + (uint32_t)(buf * 128 * 36 + r * 36 + c) * 4,
                 &A[(size_t)(m0 + r) * K + k0 + c]);
        }
        if (!TRANSB) {
            #pragma unroll
            for (int i = 0; i < 2; i++) {
                int idx = tid + i * 256;
                int r = idx >> 4, c = (idx & 15) * 4;
                cp16(bs_b + (uint32_t)(buf * 2304 + r * 72 + c) * 4,
                     &B[(size_t)(k0 + r) * N + n0 + c]);
            }
        } else {
            #pragma unroll
            for (int i = 0; i < 2; i++) {
                int idx = tid + i * 256;
                int r = idx >> 3, c = (idx & 7) * 4;
                cp16(bs_b + (uint32_t)(buf * 2304 + r * 36 + c) * 4,
                     &B[(size_t)(n0 + r) * K + k0 + c]);
            }
        }
        cp_commit();
    };

    const int nk = K / 32;
    loadTiles(0, 0);
    loadTiles(32, 1);

    int buf = 0;
    for (int ik = 0; ik < nk; ik++) {
        if (ik == nk - 1) cp_wait0(); else cp_wait1();
        __syncthreads();
        if (ik + 2 < nk) {
            int nb = buf + 2; if (nb >= 3) nb -= 3;
            loadTiles((ik + 2) * 32, nb);
        }

        const float* as = As + buf * 128 * 36;
        const float* bs = Bs + buf * 2304;

        #pragma unroll
        for (int kk = 0; kk < 4; kk++) {
            const int kc = kk * 8;
            float a[2][4], b[4][2];
            #pragma unroll
            for (int am = 0; am < 2; am++) {
                int r = wm * 32 + am * 16;
                a[am][0] = tf32r(as[(r + g) * 36 + kc + t]);
                a[am][1] = tf32r(as[(r + g + 8) * 36 + kc + t]);
                a[am][2] = tf32r(as[(r + g) * 36 + kc + t + 4]);
                a[am][3] = tf32r(as[(r + g + 8) * 36 + kc + t + 4]);
            }
            #pragma unroll
            for (int j = 0; j < 4; j++) {
                int cb = wn * 32 + 8 * j + g;
                if (!TRANSB) {
                    b[j][0] = tf32r(bs[(kc + t) * 72 + cb]);
                    b[j][1] = tf32r(bs[(kc + t + 4) * 72 + cb]);
                } else {
                    b[j][0] = tf32r(bs[cb * 36 + kc + t]);
                    b[j][1] = tf32r(bs[cb * 36 + kc + t + 4]);
                }
            }
            #pragma unroll
            for (int am = 0; am < 2; am++)
                #pragma unroll
                for (int j = 0; j < 4; j++)
                    mma8(acc[am][j], a[am][0], a[am][1], a[am][2], a[am][3],
                         b[j][0], b[j][1]);
        }
        __syncthreads();
        if (++buf == 3) buf = 0;
    }

    #pragma unroll
    for (int am = 0; am < 2; am++) {
        int r0 = m0 + wm * 32 + am * 16 + g;
        int r1 = r0 + 8;
        #pragma unroll
        for (int j = 0; j < 4; j++) {
            int c0 = n0 + wn * 32 + 8 * j + 2 * t;
            float v00 = acc[am][j][0], v01 = acc[am][j][1];
            float v10 = acc[am][j][2], v11 = acc[am][j][3];
            if (EPI == 0) {
                C[(size_t)r0 * N + c0]     = v00 + bias[c0];
                C[(size_t)r0 * N + c0 + 1] = v01 + bias[c0 + 1];
                C[(size_t)r1 * N + c0]     = v10 + bias[c0];
                C[(size_t)r1 * N + c0 + 1] = v11 + bias[c0 + 1];
            } else if (EPI == 1) {
                C[(size_t)r0 * N + c0]     = v00 + bias[c0]     + R[(size_t)r0 * N + c0];
                C[(size_t)r0 * N + c0 + 1] = v01 + bias[c0 + 1] + R[(size_t)r0 * N + c0 + 1];
                C[(size_t)r1 * N + c0]     = v10 + bias[c0]     + R[(size_t)r1 * N + c0];
                C[(size_t)r1 * N + c0 + 1] = v11 + bias[c0 + 1] + R[(size_t)r1 * N + c0 + 1];
            } else {
                float s00 = v00 / (1.f + __expf(-v00));
                float s01 = v01 / (1.f + __expf(-v01));
                float s10 = v10 / (1.f + __expf(-v10));
                float s11 = v11 / (1.f + __expf(-v11));
                C[(size_t)(c0)     * M + r0] = s00;
                C[(size_t)(c0 + 1) * M + r0] = s01;
                C[(size_t)(c0)     * M + r1] = s10;
                C[(size_t)(c0 + 1) * M + r1] = s11;
            }
        }
    }
}

// ---------------- TF32 flash attention (q-tile 128, Q in smem, no P tile) --------
// grid (LQ/128, NHEAD), 256 threads (8 warps x 16 q-rows).
// K/V: 2 buffers, prefetch depth 1 (tile kb+1 issued while computing kb).
// smem: Qs[128*72] (pair-permuted) | Ks[2][64*76] | Vs[2][64*72]
#define KS_STRIDE 76
#define VS_STRIDE 72
#define KS_TILE (64 * KS_STRIDE)
#define VS_TILE (64 * VS_STRIDE)
#define QS_FLOATS (128 * 72)
#define ATTN_SMEM_BYTES ((QS_FLOATS + 2 * KS_TILE + 2 * VS_TILE) * 4)

__global__ __launch_bounds__(256, 2)
void attn_tf32(const float* __restrict__ qkv, float* __restrict__ o_out) {
    extern __shared__ float sm[];
    float* Qs = sm;                          // [128][72], cols pair-permuted per 8-atom
    float* Ks = sm + QS_FLOATS;              // [2][64*76]
    float* Vs = sm + QS_FLOATS + 2 * KS_TILE;// [2][64*72]
    const uint32_t ks_b = (uint32_t)__cvta_generic_to_shared(Ks);
    const uint32_t vs_b = (uint32_t)__cvta_generic_to_shared(Vs);

    const int tid = threadIdx.x;
    const int lane = tid & 31;
    const int wid = tid >> 5;
    const int g = lane >> 2, t = lane & 3;
    const int h = blockIdx.y;
    const int q0 = blockIdx.x * 128;
    const int wr = wid * 16;
    const float scale = rsqrtf((float)DHEAD);
    const int lane_lo = (lane & 28) | (t >> 1);
    const int lane_hi = lane_lo + 2;
    const bool sel = (t & 1);

    auto loadKV = [&](int kb, int buf) {
        const float* base = qkv + (size_t)(kb * 64) * TD + h * DHEAD;
        #pragma unroll
        for (int i = 0; i < 5; i++) {
            int idx = tid + i * 256;
            if (i == 4 && idx >= 1152) break;
            int r = idx / 18, c = (idx - r * 18) * 4;
            const float* rp = base + (size_t)r * TD + c;
            cp16(ks_b + (uint32_t)(buf * KS_TILE + r * KS_STRIDE + c) * 4, rp + DMODEL);
            cp16(vs_b + (uint32_t)(buf * VS_TILE + r * VS_STRIDE + c) * 4, rp + 2 * DMODEL);
        }
        cp_commit();
    };

    loadKV(0, 0);

    // Q: load 128x72, scale, rna-round, store pair-permuted:
    // dest col d (atom ka, pos p): source col = 8ka + ((p&1) ? (p>>1)+4 : (p>>1))
    for (int idx = tid; idx < 128 * 72; idx += 256) {
        int r = idx / 72, d = idx - r * 72;
        int ka = d >> 3, p = d & 7;
        int dsrc = 8 * ka + ((p & 1) ? (p >> 1) + 4 : (p >> 1));
        Qs[r * 72 + d] = tf32r(qkv[(size_t)(q0 + r) * TD + h * DHEAD + dsrc] * scale);
    }

    float oacc[9][4] = {};
    float m0 = -INFINITY, m1 = -INFINITY, l0 = 0.f, l1 = 0.f;

    for (int kb = 0; kb < 64; kb++) {
        cp_wait0();
        __syncthreads();
        if (kb + 1 < 64) loadKV(kb + 1, (kb + 1) & 1);

        const float* ks = Ks + (kb & 1) * KS_TILE;
        const float* vs = Vs + (kb & 1) * VS_TILE;

        // S = Q K^T
        float sc[8][4] = {};
        #pragma unroll
        for (int ka = 0; ka < 9; ka++) {
            float2 aA = *(const float2*)&Qs[(wr + g) * 72 + 8 * ka + 2 * t];     // a0, a2
            float2 aB = *(const float2*)&Qs[(wr + g + 8) * 72 + 8 * ka + 2 * t]; // a1, a3
            #pragma unroll
            for (int j = 0; j < 8; j++) {
                const float* kr = &ks[(8 * j + g) * KS_STRIDE + ka * 8 + t];
                mma8(sc[j], aA.x, aB.x, aA.y, aB.y, kr[0], kr[4]);
            }
        }

        // online softmax (rows wr+g via c0/c1, wr+g+8 via c2/c3; quad = 4 t-lanes)
        float mx0 = -INFINITY, mx1 = -INFINITY;
        #pragma unroll
        for (int j = 0; j < 8; j++) {
            mx0 = fmaxf(mx0, fmaxf(sc[j][0], sc[j][1]));
            mx1 = fmaxf(mx1, fmaxf(sc[j][2], sc[j][3]));
        }
        mx0 = fmaxf(mx0, __shfl_xor_sync(0xffffffffu, mx0, 1));
        mx0 = fmaxf(mx0, __shfl_xor_sync(0xffffffffu, mx0, 2));
        mx1 = fmaxf(mx1, __shfl_xor_sync(0xffffffffu, mx1, 1));
        mx1 = fmaxf(mx1, __shfl_xor_sync(0xffffffffu, mx1, 2));

        float mn0 = fmaxf(m0, mx0), mn1 = fmaxf(m1, mx1);
        float al0 = __expf(m0 - mn0), al1 = __expf(m1 - mn1);
        m0 = mn0; m1 = mn1;

        float s0 = 0.f, s1 = 0.f;
        #pragma unroll
        for (int j = 0; j < 8; j++) {
            sc[j][0] = __expf(sc[j][0] - m0);
            sc[j][1] = __expf(sc[j][1] - m0);
            sc[j][2] = __expf(sc[j][2] - m1);
            sc[j][3] = __expf(sc[j][3] - m1);
            s0 += sc[j][0] + sc[j][1];
            s1 += sc[j][2] + sc[j][3];
        }
        s0 += __shfl_xor_sync(0xffffffffu, s0, 1);
        s0 += __shfl_xor_sync(0xffffffffu, s0, 2);
        s1 += __shfl_xor_sync(0xffffffffu, s1, 1);
        s1 += __shfl_xor_sync(0xffffffffu, s1, 2);
        l0 = l0 * al0 + s0;
        l1 = l1 * al1 + s1;

        #pragma unroll
        for (int j2 = 0; j2 < 9; j2++) {
            oacc[j2][0] *= al0; oacc[j2][1] *= al0;
            oacc[j2][2] *= al1; oacc[j2][3] *= al1;
        }

        // O += P V : transpose P (C-frag -> A-frag) via shuffles, per k-atom
        #pragma unroll
        for (int ka = 0; ka < 8; ka++) {
            float v0 = __shfl_sync(0xffffffffu, sc[ka][0], lane_lo);
            float v1 = __shfl_sync(0xffffffffu, sc[ka][1], lane_lo);
            float v2 = __shfl_sync(0xffffffffu, sc[ka][2], lane_lo);
            float v3 = __shfl_sync(0xffffffffu, sc[ka][3], lane_lo);
            float u0 = __shfl_sync(0xffffffffu, sc[ka][0], lane_hi);
            float u1 = __shfl_sync(0xffffffffu, sc[ka][1], lane_hi);
            float u2 = __shfl_sync(0xffffffffu, sc[ka][2], lane_hi);
            float u3 = __shfl_sync(0xffffffffu, sc[ka][3], lane_hi);
            float a0 = sel ? v1 : v0;   // P[g][8ka+t]
            float a1 = sel ? v3 : v2;   // P[g+8][8ka+t]
            float a2 = sel ? u1 : u0;   // P[g][8ka+t+4]
            float a3 = sel ? u3 : u2;   // P[g+8][8ka+t+4]
            #pragma unroll
            for (int j2 = 0; j2 < 9; j2++) {
                const float* vr = &vs[(8 * ka + t) * VS_STRIDE + 8 * j2 + g];
                mma8(oacc[j2], a0, a1, a2, a3, vr[0], vr[4 * VS_STRIDE]);
            }
        }
    }

    // finalize
    float i0 = 1.f / l0, i1 = 1.f / l1;
    float* d0 = o_out + (size_t)(q0 + wr + g) * DMODEL + h * DHEAD;
    float* d1 = d0 + 8 * (size_t)DMODEL;
    #pragma unroll
    for (int j2 = 0; j2 < 9; j2++) {
        *(float2*)&d0[8 * j2 + 2 * t] = make_float2(oacc[j2][0] * i0, oacc[j2][1] * i0);
        *(float2*)&d1[8 * j2 + 2 * t] = make_float2(oacc[j2][2] * i1, oacc[j2][3] * i1);
    }
}

// ---------------- launch ----------------
extern "C" void kernel_launch(void* const* d_in, const int* in_sizes, int n_in,
                              void* d_out, int out_size) {
    const float* fea    = (const float*)d_in[0];
    const float* w_qkv  = (const float*)d_in[1];
    const float* b_qkv  = (const float*)d_in[2];
    const float* w_out  = (const float*)d_in[3];
    const float* b_out  = (const float*)d_in[4];
    const float* conv_w = (const float*)d_in[5];
    float* out = (float*)d_out;

    float *px, *pqkv, *po, *py;
    cudaGetSymbolAddress((void**)&px,   g_x);
    cudaGetSymbolAddress((void**)&pqkv, g_qkv);
    cudaGetSymbolAddress((void**)&po,   g_o);
    cudaGetSymbolAddress((void**)&py,   g_y);

    cudaFuncSetAttribute(gemm_tf32<0, 0>, cudaFuncAttributeMaxDynamicSharedMemorySize, GEMM_SMEM_BYTES);
    cudaFuncSetAttribute(gemm_tf32<0, 1>, cudaFuncAttributeMaxDynamicSharedMemorySize, GEMM_SMEM_BYTES);
    cudaFuncSetAttribute(gemm_tf32<1, 2>, cudaFuncAttributeMaxDynamicSharedMemorySize, GEMM_SMEM_BYTES);
    cudaFuncSetAttribute(attn_tf32, cudaFuncAttributeMaxDynamicSharedMemorySize, ATTN_SMEM_BYTES);

    // 1) unfold
    unfold_kernel<<<(LQ * DMODEL + 255) / 256, 256>>>(fea);

    // 2) qkv = x @ w_qkv + b
    gemm_tf32<0, 0><<<dim3(TD / 64, LQ / 128), 256, GEMM_SMEM_BYTES>>>(
        px, w_qkv, b_qkv, nullptr, pqkv, LQ, TD, DMODEL);

    // 3) attention
    attn_tf32<<<dim3(LQ / 128, NHEAD), 256, ATTN_SMEM_BYTES>>>(pqkv, po);

    // 4) y = o @ w_out + b + x
    gemm_tf32<0, 1><<<dim3(DMODEL / 64, LQ / 128), 256, GEMM_SMEM_BYTES>>>(
        po, w_out, b_out, px, py, LQ, DMODEL, DMODEL);

    // 5) out = silu(y @ conv_w^T), stored [128, 4096]
    gemm_tf32<1, 2><<<dim3(OUTC / 64, LQ / 128), 256, GEMM_SMEM_BYTES>>>(
        py, conv_w, nullptr, nullptr, out, LQ, OUTC, DMODEL);
}